// round 16
// baseline (speedup 1.0000x reference)
#include <cuda_runtime.h>
#include <cstddef>

#define N_NODES 100000
#define N_EDGES 3200000
#define D_IN    128
#define D_HID   128
#define D_OUT   64
#define NBLK    391           // ceil(N_NODES / 256)

// ---------------- scratch (no allocation allowed) ----------------
__device__ __align__(16) float g_agg1[(size_t)N_NODES * D_IN];   // mean-agg of x
__device__ __align__(16) float g_t   [(size_t)N_NODES * D_OUT];  // h @ W_l2^T
__device__ __align__(16) float g_r   [(size_t)N_NODES * D_OUT];  // h @ W_r2^T + b2
__device__ __align__(16) float g_h   [(size_t)N_NODES * D_HID];  // fallback h storage
__device__ int  g_deg [N_NODES];
__device__ int  g_off [N_NODES + 1];
__device__ int  g_pos [N_NODES];
__device__ int  g_bsum[NBLK];
__device__ __align__(16) int2 g_edge[N_EDGES];                   // (src, w-bits), dst-grouped
__device__ int  g_idx64;   // 1 if edge_index is int64, 0 if int32

// ---------------- helpers ----------------
__device__ __forceinline__ float tf32r(float v) {
    unsigned u;
    asm("cvt.rna.tf32.f32 %0, %1;" : "=r"(u) : "f"(v));
    return __uint_as_float(u);
}
__device__ __forceinline__ void mma_tf32(float& c0, float& c1, float& c2, float& c3,
                                         unsigned a0, unsigned a1, unsigned a2, unsigned a3,
                                         unsigned b0, unsigned b1) {
    asm("mma.sync.aligned.m16n8k8.row.col.f32.tf32.tf32.f32 "
        "{%0,%1,%2,%3}, {%4,%5,%6,%7}, {%8,%9}, {%0,%1,%2,%3};"
        : "+f"(c0), "+f"(c1), "+f"(c2), "+f"(c3)
        : "r"(a0), "r"(a1), "r"(a2), "r"(a3), "r"(b0), "r"(b1));
}

__device__ __forceinline__ int load_idx(const void* ei, int e, int half, int mode64) {
    if (mode64) {
        long long v = __ldg(reinterpret_cast<const long long*>(ei) +
                            (size_t)half * N_EDGES + e);
        return (int)v;
    } else {
        return __ldg(reinterpret_cast<const int*>(ei) + (size_t)half * N_EDGES + e);
    }
}

__device__ __forceinline__ void load_idx4(const void* ei, int q, int half, int mode64,
                                          int& i0, int& i1, int& i2, int& i3) {
    if (mode64) {
        const longlong2* p = reinterpret_cast<const longlong2*>(
            reinterpret_cast<const long long*>(ei) + (size_t)half * N_EDGES) + q * 2;
        longlong2 a = __ldg(p);
        longlong2 b = __ldg(p + 1);
        i0 = (int)a.x; i1 = (int)a.y; i2 = (int)b.x; i3 = (int)b.y;
    } else {
        int4 d = __ldg(reinterpret_cast<const int4*>(
            reinterpret_cast<const int*>(ei) + (size_t)half * N_EDGES) + q);
        i0 = d.x; i1 = d.y; i2 = d.z; i3 = d.w;
    }
}

// ---------------- dtype detection + zero deg (merged) ----------------
__global__ void detect_zero_kernel(const int* __restrict__ ei_words) {
    int i = blockIdx.x * 256 + threadIdx.x;
    if (i < N_NODES) g_deg[i] = 0;
    if (blockIdx.x == 0) {
        __shared__ int any_nonzero;
        if (threadIdx.x == 0) any_nonzero = 0;
        __syncthreads();
        int acc = 0;
        for (int k = threadIdx.x; k < 4096; k += 256)
            acc |= ei_words[2 * k + 1];
        if (acc) atomicOr(&any_nonzero, 1);
        __syncthreads();
        if (threadIdx.x == 0) g_idx64 = any_nonzero ? 0 : 1;
    }
}

// ---------------- CSR build ----------------
__global__ void hist_kernel(const void* __restrict__ ei) {
    int q = blockIdx.x * blockDim.x + threadIdx.x;
    if (q >= N_EDGES / 4) return;
    int mode64 = g_idx64;
    int d0, d1, d2, d3;
    load_idx4(ei, q, 1, mode64, d0, d1, d2, d3);
    if ((unsigned)d0 < N_NODES) atomicAdd(&g_deg[d0], 1);
    if ((unsigned)d1 < N_NODES) atomicAdd(&g_deg[d1], 1);
    if ((unsigned)d2 < N_NODES) atomicAdd(&g_deg[d2], 1);
    if ((unsigned)d3 < N_NODES) atomicAdd(&g_deg[d3], 1);
}

__global__ void blocksum_kernel() {
    __shared__ int s[256];
    int i = blockIdx.x * 256 + threadIdx.x;
    s[threadIdx.x] = (i < N_NODES) ? g_deg[i] : 0;
    __syncthreads();
    for (int d = 128; d > 0; d >>= 1) {
        if (threadIdx.x < d) s[threadIdx.x] += s[threadIdx.x + d];
        __syncthreads();
    }
    if (threadIdx.x == 0) g_bsum[blockIdx.x] = s[0];
}

__global__ void offsets_kernel() {
    __shared__ int bs[512];
    __shared__ int s[512];
    int t = threadIdx.x;
    int bv = (t < NBLK) ? g_bsum[t] : 0;
    bs[t] = bv;
    __syncthreads();
    for (int d = 1; d < 512; d <<= 1) {
        int tmp = (t >= d) ? bs[t - d] : 0;
        __syncthreads();
        bs[t] += tmp;
        __syncthreads();
    }
    int bpre = (blockIdx.x == 0) ? 0 : bs[blockIdx.x - 1];
    if (blockIdx.x == 0 && t == 0) g_off[N_NODES] = bs[NBLK - 1];
    int i = blockIdx.x * 256 + t;
    int v = (t < 256 && i < N_NODES) ? g_deg[i] : 0;
    s[t] = v;
    __syncthreads();
    for (int d = 1; d < 512; d <<= 1) {
        int tmp = (t >= d) ? s[t - d] : 0;
        __syncthreads();
        s[t] += tmp;
        __syncthreads();
    }
    if (t < 256 && i < N_NODES) {
        int off = bpre + s[t] - v;
        g_off[i] = off;
        g_pos[i] = off;
    }
}

__global__ void fill_kernel(const void* __restrict__ ei,
                            const float* __restrict__ ew) {
    int q = blockIdx.x * blockDim.x + threadIdx.x;
    if (q >= N_EDGES / 4) return;
    int mode64 = g_idx64;
    int s0, s1, s2, s3, d0, d1, d2, d3;
    load_idx4(ei, q, 0, mode64, s0, s1, s2, s3);
    load_idx4(ei, q, 1, mode64, d0, d1, d2, d3);
    float4 w = __ldg(reinterpret_cast<const float4*>(ew) + q);
    if ((unsigned)s0 < N_NODES && (unsigned)d0 < N_NODES) {
        int p = atomicAdd(&g_pos[d0], 1);
        g_edge[p] = make_int2(s0, __float_as_int(w.x));
    }
    if ((unsigned)s1 < N_NODES && (unsigned)d1 < N_NODES) {
        int p = atomicAdd(&g_pos[d1], 1);
        g_edge[p] = make_int2(s1, __float_as_int(w.y));
    }
    if ((unsigned)s2 < N_NODES && (unsigned)d2 < N_NODES) {
        int p = atomicAdd(&g_pos[d2], 1);
        g_edge[p] = make_int2(s2, __float_as_int(w.z));
    }
    if ((unsigned)s3 < N_NODES && (unsigned)d3 < N_NODES) {
        int p = atomicAdd(&g_pos[d3], 1);
        g_edge[p] = make_int2(s3, __float_as_int(w.w));
    }
}

// ---------------- gather1: agg1[n] = mean over in-edges of x[src]*w ----------------
// TWO warps per node: warp parity selects 64-feature half; lane covers 2 features
// (float2). Fewer regs -> higher occupancy -> better latency hiding.
// batches of 4 with cross-batch edge prefetch (proven sweet spot).
__global__ void gather1_kernel(const float* __restrict__ x) {
    int w = (blockIdx.x * blockDim.x + threadIdx.x) >> 5;
    int n = w >> 1;
    if (n >= N_NODES) return;
    int half = w & 1;
    int lane = threadIdx.x & 31;
    int fo = half * 64 + lane * 2;            // feature offset
    const float* xb = x + fo;
    int off = g_off[n], end = g_off[n + 1];
    float2 a0 = make_float2(0.f, 0.f), a1 = a0, a2 = a0, a3 = a0;
    int i = off;
    int2 e0, e1, e2, e3;
    bool have = (i + 4 <= end);
    if (have) {
        e0 = __ldg(reinterpret_cast<const int2*>(g_edge) + i + 0);
        e1 = __ldg(reinterpret_cast<const int2*>(g_edge) + i + 1);
        e2 = __ldg(reinterpret_cast<const int2*>(g_edge) + i + 2);
        e3 = __ldg(reinterpret_cast<const int2*>(g_edge) + i + 3);
    }
    for (; i + 8 <= end; i += 4) {
        int2 f0 = __ldg(reinterpret_cast<const int2*>(g_edge) + i + 4);
        int2 f1 = __ldg(reinterpret_cast<const int2*>(g_edge) + i + 5);
        int2 f2 = __ldg(reinterpret_cast<const int2*>(g_edge) + i + 6);
        int2 f3 = __ldg(reinterpret_cast<const int2*>(g_edge) + i + 7);
        float2 v0 = __ldg(reinterpret_cast<const float2*>(xb + (size_t)e0.x * D_IN));
        float2 v1 = __ldg(reinterpret_cast<const float2*>(xb + (size_t)e1.x * D_IN));
        float2 v2 = __ldg(reinterpret_cast<const float2*>(xb + (size_t)e2.x * D_IN));
        float2 v3 = __ldg(reinterpret_cast<const float2*>(xb + (size_t)e3.x * D_IN));
        float w0 = __int_as_float(e0.y), w1 = __int_as_float(e1.y);
        float w2 = __int_as_float(e2.y), w3 = __int_as_float(e3.y);
        a0.x = fmaf(v0.x, w0, a0.x); a0.y = fmaf(v0.y, w0, a0.y);
        a1.x = fmaf(v1.x, w1, a1.x); a1.y = fmaf(v1.y, w1, a1.y);
        a2.x = fmaf(v2.x, w2, a2.x); a2.y = fmaf(v2.y, w2, a2.y);
        a3.x = fmaf(v3.x, w3, a3.x); a3.y = fmaf(v3.y, w3, a3.y);
        e0 = f0; e1 = f1; e2 = f2; e3 = f3;
    }
    if (have) {
        float2 v0 = __ldg(reinterpret_cast<const float2*>(xb + (size_t)e0.x * D_IN));
        float2 v1 = __ldg(reinterpret_cast<const float2*>(xb + (size_t)e1.x * D_IN));
        float2 v2 = __ldg(reinterpret_cast<const float2*>(xb + (size_t)e2.x * D_IN));
        float2 v3 = __ldg(reinterpret_cast<const float2*>(xb + (size_t)e3.x * D_IN));
        float w0 = __int_as_float(e0.y), w1 = __int_as_float(e1.y);
        float w2 = __int_as_float(e2.y), w3 = __int_as_float(e3.y);
        a0.x = fmaf(v0.x, w0, a0.x); a0.y = fmaf(v0.y, w0, a0.y);
        a1.x = fmaf(v1.x, w1, a1.x); a1.y = fmaf(v1.y, w1, a1.y);
        a2.x = fmaf(v2.x, w2, a2.x); a2.y = fmaf(v2.y, w2, a2.y);
        a3.x = fmaf(v3.x, w3, a3.x); a3.y = fmaf(v3.y, w3, a3.y);
        i += 4;
    }
    for (; i < end; ++i) {
        int2 e = __ldg(reinterpret_cast<const int2*>(g_edge) + i);
        float w2 = __int_as_float(e.y);
        float2 v = __ldg(reinterpret_cast<const float2*>(xb + (size_t)e.x * D_IN));
        a0.x = fmaf(v.x, w2, a0.x); a0.y = fmaf(v.y, w2, a0.y);
    }
    a0.x += (a1.x + a2.x) + a3.x;
    a0.y += (a1.y + a2.y) + a3.y;
    float inv = 1.0f / fmaxf((float)(end - off), 1.0f);
    a0.x *= inv; a0.y *= inv;
    *reinterpret_cast<float2*>(g_agg1 + (size_t)n * D_IN + fo) = a0;
}

// ---------------- layer 1 (tensor-core tf32 mma): h = relu([agg1|x] @ [Wl|Wr]^T + b) ----
#define LTC_WFLOATS (16 * 32 * 32 * 2)     // 32768 floats = 128 KB
#define LTC_FFLOATS (4 * 32 * 32 * 4)      // 16384 floats = 64 KB
#define LTC_SMEM_BYTES ((LTC_WFLOATS + LTC_FFLOATS) * 4)   // 196608
__global__ void layer1_tc_kernel(const float* __restrict__ x,
                                 const float* __restrict__ Wl,
                                 const float* __restrict__ bl,
                                 const float* __restrict__ Wr,
                                 float* __restrict__ hout) {
    extern __shared__ float sm[];
    float* Wf = sm;
    float* Ff = sm + LTC_WFLOATS;
    int t = threadIdx.x;

    for (int it = t; it < 128 * 64; it += 512) {
        int j = it >> 6, k4 = it & 63;
        int k0 = k4 * 4;
        float4 v = (k0 < 128)
            ? __ldg(reinterpret_cast<const float4*>(Wl + (size_t)j * 128 + k0))
            : __ldg(reinterpret_cast<const float4*>(Wr + (size_t)j * 128 + (k0 - 128)));
        int n_tile = j >> 3, g = j & 7;
        int ks = k0 >> 3, slot = (k0 & 7) >> 2;
        float* dst = Wf + ((n_tile * 32 + ks) * 32) * 2 + slot;
        int Lb = g * 4;
        dst[(Lb + 0) * 2] = tf32r(v.x);
        dst[(Lb + 1) * 2] = tf32r(v.y);
        dst[(Lb + 2) * 2] = tf32r(v.z);
        dst[(Lb + 3) * 2] = tf32r(v.w);
    }
    int warp = t >> 5, L = t & 31;
    int mw = warp >> 2, nw = warp & 3;
    int g = L >> 2, tg = L & 3;
    __syncthreads();

    const int NT = (N_NODES + 63) / 64;      // 1563
    for (int tile = blockIdx.x; tile < NT; tile += gridDim.x) {
        int base = tile * 64;
        __syncthreads();
        for (int it = t; it < 64 * 64; it += 512) {
            int nn = it >> 6, k4 = it & 63;
            int node = base + nn; if (node >= N_NODES) node = N_NODES - 1;
            int k0 = k4 * 4;
            float4 v = (k0 < 128)
                ? *reinterpret_cast<const float4*>(g_agg1 + (size_t)node * 128 + k0)
                : __ldg(reinterpret_cast<const float4*>(x + (size_t)node * 128 + (k0 - 128)));
            int m_tile = nn >> 4, r = nn & 15;
            int gg = r & 7, rowhi = r >> 3;
            int ks = k0 >> 3, colhi = (k0 & 7) >> 2;
            int f = rowhi + 2 * colhi;
            float* dst = Ff + ((m_tile * 32 + ks) * 32) * 4 + f;
            int Lb = gg * 4;
            dst[(Lb + 0) * 4] = tf32r(v.x);
            dst[(Lb + 1) * 4] = tf32r(v.y);
            dst[(Lb + 2) * 4] = tf32r(v.z);
            dst[(Lb + 3) * 4] = tf32r(v.w);
        }
        __syncthreads();
        float c[4][4];
        #pragma unroll
        for (int nt = 0; nt < 4; ++nt)
            c[nt][0] = c[nt][1] = c[nt][2] = c[nt][3] = 0.f;
        const float* fa = Ff + (mw * 32) * 128 + L * 4;
        #pragma unroll 4
        for (int ks = 0; ks < 32; ++ks) {
            float4 av = *reinterpret_cast<const float4*>(fa + ks * 128);
            unsigned a0 = __float_as_uint(av.x), a1 = __float_as_uint(av.y);
            unsigned a2 = __float_as_uint(av.z), a3 = __float_as_uint(av.w);
            #pragma unroll
            for (int nt = 0; nt < 4; ++nt) {
                const float* fb = Wf + ((nw * 4 + nt) * 32 + ks) * 64 + L * 2;
                float2 bv = *reinterpret_cast<const float2*>(fb);
                mma_tf32(c[nt][0], c[nt][1], c[nt][2], c[nt][3],
                         a0, a1, a2, a3,
                         __float_as_uint(bv.x), __float_as_uint(bv.y));
            }
        }
        int n0 = base + mw * 16 + g;
        int n1 = n0 + 8;
        #pragma unroll
        for (int nt = 0; nt < 4; ++nt) {
            int j0 = nw * 32 + nt * 8 + tg * 2;
            float b0 = __ldg(&bl[j0]), b1 = __ldg(&bl[j0 + 1]);
            if (n0 < N_NODES) {
                float2 o = make_float2(fmaxf(c[nt][0] + b0, 0.f),
                                       fmaxf(c[nt][1] + b1, 0.f));
                *reinterpret_cast<float2*>(&hout[(size_t)n0 * 128 + j0]) = o;
            }
            if (n1 < N_NODES) {
                float2 o = make_float2(fmaxf(c[nt][2] + b0, 0.f),
                                       fmaxf(c[nt][3] + b1, 0.f));
                *reinterpret_cast<float2*>(&hout[(size_t)n1 * 128 + j0]) = o;
            }
        }
    }
}

// ---------------- tmat2 (tensor-core tf32 mma, fused): [t|r] = h @ [Wl2|Wr2]^T -------
#define T2C_WFLOATS (16 * 16 * 32 * 2)     // 16384 floats = 64 KB
#define T2C_FFLOATS (4 * 16 * 32 * 4)      // 8192 floats = 32 KB
#define T2C_SMEM_BYTES ((T2C_WFLOATS + T2C_FFLOATS) * 4)   // 98304
__global__ void tmat2_tc_kernel(const float* __restrict__ h,
                                const float* __restrict__ Wl2,
                                const float* __restrict__ Wr2,
                                const float* __restrict__ b2) {
    extern __shared__ float sm[];
    float* Wf = sm;
    float* Ff = sm + T2C_WFLOATS;
    int t = threadIdx.x;

    for (int it = t; it < 128 * 32; it += 512) {
        int j = it >> 5, k4 = it & 31;
        int k0 = k4 * 4;
        float4 v = (j < 64)
            ? __ldg(reinterpret_cast<const float4*>(Wl2 + (size_t)j * 128 + k0))
            : __ldg(reinterpret_cast<const float4*>(Wr2 + (size_t)(j - 64) * 128 + k0));
        int n_tile = j >> 3, g = j & 7;
        int ks = k0 >> 3, slot = (k0 & 7) >> 2;
        float* dst = Wf + ((n_tile * 16 + ks) * 32) * 2 + slot;
        int Lb = g * 4;
        dst[(Lb + 0) * 2] = tf32r(v.x);
        dst[(Lb + 1) * 2] = tf32r(v.y);
        dst[(Lb + 2) * 2] = tf32r(v.z);
        dst[(Lb + 3) * 2] = tf32r(v.w);
    }
    int warp = t >> 5, L = t & 31;
    int mw = warp >> 2, nw = warp & 3;
    int g = L >> 2, tg = L & 3;
    __syncthreads();

    const int NT = (N_NODES + 63) / 64;      // 1563
    for (int tile = blockIdx.x; tile < NT; tile += gridDim.x) {
        int base = tile * 64;
        __syncthreads();
        for (int it = t; it < 64 * 32; it += 512) {
            int nn = it >> 5, k4 = it & 31;
            int node = base + nn; if (node >= N_NODES) node = N_NODES - 1;
            int k0 = k4 * 4;
            float4 v = *reinterpret_cast<const float4*>(h + (size_t)node * 128 + k0);
            int m_tile = nn >> 4, r = nn & 15;
            int gg = r & 7, rowhi = r >> 3;
            int ks = k0 >> 3, colhi = (k0 & 7) >> 2;
            int f = rowhi + 2 * colhi;
            float* dst = Ff + ((m_tile * 16 + ks) * 32) * 4 + f;
            int Lb = gg * 4;
            dst[(Lb + 0) * 4] = tf32r(v.x);
            dst[(Lb + 1) * 4] = tf32r(v.y);
            dst[(Lb + 2) * 4] = tf32r(v.z);
            dst[(Lb + 3) * 4] = tf32r(v.w);
        }
        __syncthreads();
        float c[4][4];
        #pragma unroll
        for (int nt = 0; nt < 4; ++nt)
            c[nt][0] = c[nt][1] = c[nt][2] = c[nt][3] = 0.f;
        const float* fa = Ff + (mw * 16) * 128 + L * 4;
        #pragma unroll 4
        for (int ks = 0; ks < 16; ++ks) {
            float4 av = *reinterpret_cast<const float4*>(fa + ks * 128);
            unsigned a0 = __float_as_uint(av.x), a1 = __float_as_uint(av.y);
            unsigned a2 = __float_as_uint(av.z), a3 = __float_as_uint(av.w);
            #pragma unroll
            for (int nt = 0; nt < 4; ++nt) {
                const float* fb = Wf + ((nw * 4 + nt) * 16 + ks) * 64 + L * 2;
                float2 bv = *reinterpret_cast<const float2*>(fb);
                mma_tf32(c[nt][0], c[nt][1], c[nt][2], c[nt][3],
                         a0, a1, a2, a3,
                         __float_as_uint(bv.x), __float_as_uint(bv.y));
            }
        }
        int n0 = base + mw * 16 + g;
        int n1 = n0 + 8;
        #pragma unroll
        for (int nt = 0; nt < 4; ++nt) {
            int j0 = nw * 32 + nt * 8 + tg * 2;
            if (j0 < 64) {
                if (n0 < N_NODES)
                    *reinterpret_cast<float2*>(&g_t[(size_t)n0 * 64 + j0]) =
                        make_float2(c[nt][0], c[nt][1]);
                if (n1 < N_NODES)
                    *reinterpret_cast<float2*>(&g_t[(size_t)n1 * 64 + j0]) =
                        make_float2(c[nt][2], c[nt][3]);
            } else {
                int jr = j0 - 64;
                float b0 = __ldg(&b2[jr]), b1 = __ldg(&b2[jr + 1]);
                if (n0 < N_NODES)
                    *reinterpret_cast<float2*>(&g_r[(size_t)n0 * 64 + jr]) =
                        make_float2(c[nt][0] + b0, c[nt][1] + b1);
                if (n1 < N_NODES)
                    *reinterpret_cast<float2*>(&g_r[(size_t)n1 * 64 + jr]) =
                        make_float2(c[nt][2] + b0, c[nt][3] + b1);
            }
        }
    }
}

// ---------------- gather2 + epilogue: out = mean-agg(t) + r ----------------
// ONE warp per node; lane covers 2 features (float2); batches of 4 with prefetch.
__global__ void gather2_kernel(float* __restrict__ out) {
    int n = (blockIdx.x * blockDim.x + threadIdx.x) >> 5;
    if (n >= N_NODES) return;
    int lane = threadIdx.x & 31;
    int fo = lane * 2;
    const float* tb = g_t + fo;
    int off = g_off[n], end = g_off[n + 1];
    float2 rv = __ldg(reinterpret_cast<const float2*>(g_r + (size_t)n * D_OUT + fo));
    float2 a0 = make_float2(0.f, 0.f), a1 = a0, a2 = a0, a3 = a0;
    int i = off;
    int2 e0, e1, e2, e3;
    bool have = (i + 4 <= end);
    if (have) {
        e0 = __ldg(reinterpret_cast<const int2*>(g_edge) + i + 0);
        e1 = __ldg(reinterpret_cast<const int2*>(g_edge) + i + 1);
        e2 = __ldg(reinterpret_cast<const int2*>(g_edge) + i + 2);
        e3 = __ldg(reinterpret_cast<const int2*>(g_edge) + i + 3);
    }
    for (; i + 8 <= end; i += 4) {
        int2 f0 = __ldg(reinterpret_cast<const int2*>(g_edge) + i + 4);
        int2 f1 = __ldg(reinterpret_cast<const int2*>(g_edge) + i + 5);
        int2 f2 = __ldg(reinterpret_cast<const int2*>(g_edge) + i + 6);
        int2 f3 = __ldg(reinterpret_cast<const int2*>(g_edge) + i + 7);
        float2 v0 = __ldg(reinterpret_cast<const float2*>(tb + (size_t)e0.x * D_OUT));
        float2 v1 = __ldg(reinterpret_cast<const float2*>(tb + (size_t)e1.x * D_OUT));
        float2 v2 = __ldg(reinterpret_cast<const float2*>(tb + (size_t)e2.x * D_OUT));
        float2 v3 = __ldg(reinterpret_cast<const float2*>(tb + (size_t)e3.x * D_OUT));
        float w0 = __int_as_float(e0.y), w1 = __int_as_float(e1.y);
        float w2 = __int_as_float(e2.y), w3 = __int_as_float(e3.y);
        a0.x = fmaf(v0.x, w0, a0.x); a0.y = fmaf(v0.y, w0, a0.y);
        a1.x = fmaf(v1.x, w1, a1.x); a1.y = fmaf(v1.y, w1, a1.y);
        a2.x = fmaf(v2.x, w2, a2.x); a2.y = fmaf(v2.y, w2, a2.y);
        a3.x = fmaf(v3.x, w3, a3.x); a3.y = fmaf(v3.y, w3, a3.y);
        e0 = f0; e1 = f1; e2 = f2; e3 = f3;
    }
    if (have) {
        float2 v0 = __ldg(reinterpret_cast<const float2*>(tb + (size_t)e0.x * D_OUT));
        float2 v1 = __ldg(reinterpret_cast<const float2*>(tb + (size_t)e1.x * D_OUT));
        float2 v2 = __ldg(reinterpret_cast<const float2*>(tb + (size_t)e2.x * D_OUT));
        float2 v3 = __ldg(reinterpret_cast<const float2*>(tb + (size_t)e3.x * D_OUT));
        float w0 = __int_as_float(e0.y), w1 = __int_as_float(e1.y);
        float w2 = __int_as_float(e2.y), w3 = __int_as_float(e3.y);
        a0.x = fmaf(v0.x, w0, a0.x); a0.y = fmaf(v0.y, w0, a0.y);
        a1.x = fmaf(v1.x, w1, a1.x); a1.y = fmaf(v1.y, w1, a1.y);
        a2.x = fmaf(v2.x, w2, a2.x); a2.y = fmaf(v2.y, w2, a2.y);
        a3.x = fmaf(v3.x, w3, a3.x); a3.y = fmaf(v3.y, w3, a3.y);
        i += 4;
    }
    for (; i < end; ++i) {
        int2 e = __ldg(reinterpret_cast<const int2*>(g_edge) + i);
        float w2 = __int_as_float(e.y);
        float2 v = __ldg(reinterpret_cast<const float2*>(tb + (size_t)e.x * D_OUT));
        a0.x = fmaf(v.x, w2, a0.x); a0.y = fmaf(v.y, w2, a0.y);
    }
    a0.x += (a1.x + a2.x) + a3.x;
    a0.y += (a1.y + a2.y) + a3.y;
    float inv = 1.0f / fmaxf((float)(end - off), 1.0f);
    a0.x = fmaf(a0.x, inv, rv.x);
    a0.y = fmaf(a0.y, inv, rv.y);
    *reinterpret_cast<float2*>(out + (size_t)n * D_OUT + fo) = a0;
}

// ---------------- launch ----------------
extern "C" void kernel_launch(void* const* d_in, const int* in_sizes, int n_in,
                              void* d_out, int out_size) {
    (void)in_sizes; (void)n_in;
    const float* x   = (const float*)d_in[0];
    const void*  ei  = d_in[1];                 // int32 or int64, detected on device
    const float* ew  = (const float*)d_in[2];
    const float* Wl1 = (const float*)d_in[3];
    const float* bl1 = (const float*)d_in[4];
    const float* Wr1 = (const float*)d_in[5];
    const float* Wl2 = (const float*)d_in[6];
    const float* bl2 = (const float*)d_in[7];
    const float* Wr2 = (const float*)d_in[8];

    float* hptr;
    float* lptr;
    const size_t full = (size_t)N_NODES * (D_HID + D_OUT);
    if ((size_t)out_size >= full) {
        hptr = (float*)d_out;
        lptr = hptr + (size_t)N_NODES * D_HID;
    } else {
        void* sym = nullptr;
        cudaGetSymbolAddress(&sym, g_h);
        hptr = (float*)sym;
        lptr = (float*)d_out;
    }

    int smcount = 148;
    if (cudaDeviceGetAttribute(&smcount, cudaDevAttrMultiProcessorCount, 0) != cudaSuccess)
        smcount = 148;

    cudaFuncSetAttribute(layer1_tc_kernel,
                         cudaFuncAttributeMaxDynamicSharedMemorySize, LTC_SMEM_BYTES);
    cudaFuncSetAttribute(tmat2_tc_kernel,
                         cudaFuncAttributeMaxDynamicSharedMemorySize, T2C_SMEM_BYTES);

    detect_zero_kernel<<<NBLK, 256>>>((const int*)ei);       // 1
    hist_kernel<<<N_EDGES / 4 / 256, 256>>>(ei);             // 2
    blocksum_kernel<<<NBLK, 256>>>();                        // 3
    offsets_kernel<<<NBLK, 512>>>();                         // 4
    fill_kernel<<<N_EDGES / 4 / 256, 256>>>(ei, ew);         // 5
    gather1_kernel<<<(N_NODES * 64 + 255) / 256, 256>>>(x);  // 6 (2 warps/node)
    layer1_tc_kernel<<<smcount, 512, LTC_SMEM_BYTES>>>(x, Wl1, bl1, Wr1, hptr);
    tmat2_tc_kernel<<<smcount, 512, T2C_SMEM_BYTES>>>(hptr, Wl2, Wr2, bl2);
    gather2_kernel<<<(N_NODES * 32 + 255) / 256, 256>>>(lptr);
}

// round 17
// speedup vs baseline: 1.0816x; 1.0816x over previous
#include <cuda_runtime.h>
#include <cstddef>

#define N_NODES 100000
#define N_EDGES 3200000
#define D_IN    128
#define D_HID   128
#define D_OUT   64
#define NBLK    391           // ceil(N_NODES / 256)

// ---------------- scratch (no allocation allowed) ----------------
__device__ __align__(16) float g_agg1[(size_t)N_NODES * D_IN];   // mean-agg of x
__device__ __align__(16) float g_t   [(size_t)N_NODES * D_OUT];  // h @ W_l2^T
__device__ __align__(16) float g_r   [(size_t)N_NODES * D_OUT];  // h @ W_r2^T + b2
__device__ __align__(16) float g_h   [(size_t)N_NODES * D_HID];  // fallback h storage
__device__ int  g_deg [N_NODES];
__device__ int  g_off [N_NODES + 1];
__device__ int  g_pos [N_NODES];
__device__ int  g_bsum[NBLK];
__device__ __align__(16) int2 g_edge[N_EDGES];                   // (src, w-bits), dst-grouped
__device__ int  g_idx64;   // 1 if edge_index is int64, 0 if int32

// ---------------- helpers ----------------
__device__ __forceinline__ float tf32r(float v) {
    unsigned u;
    asm("cvt.rna.tf32.f32 %0, %1;" : "=r"(u) : "f"(v));
    return __uint_as_float(u);
}
__device__ __forceinline__ void mma_tf32(float& c0, float& c1, float& c2, float& c3,
                                         unsigned a0, unsigned a1, unsigned a2, unsigned a3,
                                         unsigned b0, unsigned b1) {
    asm("mma.sync.aligned.m16n8k8.row.col.f32.tf32.tf32.f32 "
        "{%0,%1,%2,%3}, {%4,%5,%6,%7}, {%8,%9}, {%0,%1,%2,%3};"
        : "+f"(c0), "+f"(c1), "+f"(c2), "+f"(c3)
        : "r"(a0), "r"(a1), "r"(a2), "r"(a3), "r"(b0), "r"(b1));
}

__device__ __forceinline__ int load_idx(const void* ei, int e, int half, int mode64) {
    if (mode64) {
        long long v = __ldg(reinterpret_cast<const long long*>(ei) +
                            (size_t)half * N_EDGES + e);
        return (int)v;
    } else {
        return __ldg(reinterpret_cast<const int*>(ei) + (size_t)half * N_EDGES + e);
    }
}

__device__ __forceinline__ void load_idx4(const void* ei, int q, int half, int mode64,
                                          int& i0, int& i1, int& i2, int& i3) {
    if (mode64) {
        const longlong2* p = reinterpret_cast<const longlong2*>(
            reinterpret_cast<const long long*>(ei) + (size_t)half * N_EDGES) + q * 2;
        longlong2 a = __ldg(p);
        longlong2 b = __ldg(p + 1);
        i0 = (int)a.x; i1 = (int)a.y; i2 = (int)b.x; i3 = (int)b.y;
    } else {
        int4 d = __ldg(reinterpret_cast<const int4*>(
            reinterpret_cast<const int*>(ei) + (size_t)half * N_EDGES) + q);
        i0 = d.x; i1 = d.y; i2 = d.z; i3 = d.w;
    }
}

// ---------------- dtype detection + zero deg (merged) ----------------
__global__ void detect_zero_kernel(const int* __restrict__ ei_words) {
    int i = blockIdx.x * 256 + threadIdx.x;
    if (i < N_NODES) g_deg[i] = 0;
    if (blockIdx.x == 0) {
        __shared__ int any_nonzero;
        if (threadIdx.x == 0) any_nonzero = 0;
        __syncthreads();
        int acc = 0;
        for (int k = threadIdx.x; k < 4096; k += 256)
            acc |= ei_words[2 * k + 1];
        if (acc) atomicOr(&any_nonzero, 1);
        __syncthreads();
        if (threadIdx.x == 0) g_idx64 = any_nonzero ? 0 : 1;
    }
}

// ---------------- CSR build ----------------
__global__ void hist_kernel(const void* __restrict__ ei) {
    int q = blockIdx.x * blockDim.x + threadIdx.x;
    if (q >= N_EDGES / 4) return;
    int mode64 = g_idx64;
    int d0, d1, d2, d3;
    load_idx4(ei, q, 1, mode64, d0, d1, d2, d3);
    if ((unsigned)d0 < N_NODES) atomicAdd(&g_deg[d0], 1);
    if ((unsigned)d1 < N_NODES) atomicAdd(&g_deg[d1], 1);
    if ((unsigned)d2 < N_NODES) atomicAdd(&g_deg[d2], 1);
    if ((unsigned)d3 < N_NODES) atomicAdd(&g_deg[d3], 1);
}

__global__ void blocksum_kernel() {
    __shared__ int s[256];
    int i = blockIdx.x * 256 + threadIdx.x;
    s[threadIdx.x] = (i < N_NODES) ? g_deg[i] : 0;
    __syncthreads();
    for (int d = 128; d > 0; d >>= 1) {
        if (threadIdx.x < d) s[threadIdx.x] += s[threadIdx.x + d];
        __syncthreads();
    }
    if (threadIdx.x == 0) g_bsum[blockIdx.x] = s[0];
}

__global__ void offsets_kernel() {
    __shared__ int bs[512];
    __shared__ int s[512];
    int t = threadIdx.x;
    int bv = (t < NBLK) ? g_bsum[t] : 0;
    bs[t] = bv;
    __syncthreads();
    for (int d = 1; d < 512; d <<= 1) {
        int tmp = (t >= d) ? bs[t - d] : 0;
        __syncthreads();
        bs[t] += tmp;
        __syncthreads();
    }
    int bpre = (blockIdx.x == 0) ? 0 : bs[blockIdx.x - 1];
    if (blockIdx.x == 0 && t == 0) g_off[N_NODES] = bs[NBLK - 1];
    int i = blockIdx.x * 256 + t;
    int v = (t < 256 && i < N_NODES) ? g_deg[i] : 0;
    s[t] = v;
    __syncthreads();
    for (int d = 1; d < 512; d <<= 1) {
        int tmp = (t >= d) ? s[t - d] : 0;
        __syncthreads();
        s[t] += tmp;
        __syncthreads();
    }
    if (t < 256 && i < N_NODES) {
        int off = bpre + s[t] - v;
        g_off[i] = off;
        g_pos[i] = off;
    }
}

__global__ void fill_kernel(const void* __restrict__ ei,
                            const float* __restrict__ ew) {
    int q = blockIdx.x * blockDim.x + threadIdx.x;
    if (q >= N_EDGES / 4) return;
    int mode64 = g_idx64;
    int s0, s1, s2, s3, d0, d1, d2, d3;
    load_idx4(ei, q, 0, mode64, s0, s1, s2, s3);
    load_idx4(ei, q, 1, mode64, d0, d1, d2, d3);
    float4 w = __ldg(reinterpret_cast<const float4*>(ew) + q);
    if ((unsigned)s0 < N_NODES && (unsigned)d0 < N_NODES) {
        int p = atomicAdd(&g_pos[d0], 1);
        g_edge[p] = make_int2(s0, __float_as_int(w.x));
    }
    if ((unsigned)s1 < N_NODES && (unsigned)d1 < N_NODES) {
        int p = atomicAdd(&g_pos[d1], 1);
        g_edge[p] = make_int2(s1, __float_as_int(w.y));
    }
    if ((unsigned)s2 < N_NODES && (unsigned)d2 < N_NODES) {
        int p = atomicAdd(&g_pos[d2], 1);
        g_edge[p] = make_int2(s2, __float_as_int(w.z));
    }
    if ((unsigned)s3 < N_NODES && (unsigned)d3 < N_NODES) {
        int p = atomicAdd(&g_pos[d3], 1);
        g_edge[p] = make_int2(s3, __float_as_int(w.w));
    }
}

// ---------------- gather1: agg1[n] = mean over in-edges of x[src]*w ----------------
// one warp per node; lane covers 4 features (float4); batches of 4 with
// cross-batch edge prefetch (calibrated optimum)
__global__ void gather1_kernel(const float* __restrict__ x) {
    int n = (blockIdx.x * blockDim.x + threadIdx.x) >> 5;
    if (n >= N_NODES) return;
    int lane = threadIdx.x & 31;
    int off = g_off[n], end = g_off[n + 1];
    float4 a0 = make_float4(0.f, 0.f, 0.f, 0.f);
    float4 a1 = a0, a2 = a0, a3 = a0;
    int i = off;
    int2 e0, e1, e2, e3;
    bool have = (i + 4 <= end);
    if (have) {
        e0 = __ldg(reinterpret_cast<const int2*>(g_edge) + i + 0);
        e1 = __ldg(reinterpret_cast<const int2*>(g_edge) + i + 1);
        e2 = __ldg(reinterpret_cast<const int2*>(g_edge) + i + 2);
        e3 = __ldg(reinterpret_cast<const int2*>(g_edge) + i + 3);
    }
    for (; i + 8 <= end; i += 4) {
        int2 f0 = __ldg(reinterpret_cast<const int2*>(g_edge) + i + 4);
        int2 f1 = __ldg(reinterpret_cast<const int2*>(g_edge) + i + 5);
        int2 f2 = __ldg(reinterpret_cast<const int2*>(g_edge) + i + 6);
        int2 f3 = __ldg(reinterpret_cast<const int2*>(g_edge) + i + 7);
        float4 v0 = __ldg(reinterpret_cast<const float4*>(x + (size_t)e0.x * D_IN) + lane);
        float4 v1 = __ldg(reinterpret_cast<const float4*>(x + (size_t)e1.x * D_IN) + lane);
        float4 v2 = __ldg(reinterpret_cast<const float4*>(x + (size_t)e2.x * D_IN) + lane);
        float4 v3 = __ldg(reinterpret_cast<const float4*>(x + (size_t)e3.x * D_IN) + lane);
        float w0 = __int_as_float(e0.y), w1 = __int_as_float(e1.y);
        float w2 = __int_as_float(e2.y), w3 = __int_as_float(e3.y);
        a0.x = fmaf(v0.x, w0, a0.x); a0.y = fmaf(v0.y, w0, a0.y);
        a0.z = fmaf(v0.z, w0, a0.z); a0.w = fmaf(v0.w, w0, a0.w);
        a1.x = fmaf(v1.x, w1, a1.x); a1.y = fmaf(v1.y, w1, a1.y);
        a1.z = fmaf(v1.z, w1, a1.z); a1.w = fmaf(v1.w, w1, a1.w);
        a2.x = fmaf(v2.x, w2, a2.x); a2.y = fmaf(v2.y, w2, a2.y);
        a2.z = fmaf(v2.z, w2, a2.z); a2.w = fmaf(v2.w, w2, a2.w);
        a3.x = fmaf(v3.x, w3, a3.x); a3.y = fmaf(v3.y, w3, a3.y);
        a3.z = fmaf(v3.z, w3, a3.z); a3.w = fmaf(v3.w, w3, a3.w);
        e0 = f0; e1 = f1; e2 = f2; e3 = f3;
    }
    if (have) {
        float4 v0 = __ldg(reinterpret_cast<const float4*>(x + (size_t)e0.x * D_IN) + lane);
        float4 v1 = __ldg(reinterpret_cast<const float4*>(x + (size_t)e1.x * D_IN) + lane);
        float4 v2 = __ldg(reinterpret_cast<const float4*>(x + (size_t)e2.x * D_IN) + lane);
        float4 v3 = __ldg(reinterpret_cast<const float4*>(x + (size_t)e3.x * D_IN) + lane);
        float w0 = __int_as_float(e0.y), w1 = __int_as_float(e1.y);
        float w2 = __int_as_float(e2.y), w3 = __int_as_float(e3.y);
        a0.x = fmaf(v0.x, w0, a0.x); a0.y = fmaf(v0.y, w0, a0.y);
        a0.z = fmaf(v0.z, w0, a0.z); a0.w = fmaf(v0.w, w0, a0.w);
        a1.x = fmaf(v1.x, w1, a1.x); a1.y = fmaf(v1.y, w1, a1.y);
        a1.z = fmaf(v1.z, w1, a1.z); a1.w = fmaf(v1.w, w1, a1.w);
        a2.x = fmaf(v2.x, w2, a2.x); a2.y = fmaf(v2.y, w2, a2.y);
        a2.z = fmaf(v2.z, w2, a2.z); a2.w = fmaf(v2.w, w2, a2.w);
        a3.x = fmaf(v3.x, w3, a3.x); a3.y = fmaf(v3.y, w3, a3.y);
        a3.z = fmaf(v3.z, w3, a3.z); a3.w = fmaf(v3.w, w3, a3.w);
        i += 4;
    }
    for (; i < end; ++i) {
        int2 e = __ldg(reinterpret_cast<const int2*>(g_edge) + i);
        float w = __int_as_float(e.y);
        float4 v = __ldg(reinterpret_cast<const float4*>(x + (size_t)e.x * D_IN) + lane);
        a0.x = fmaf(v.x, w, a0.x); a0.y = fmaf(v.y, w, a0.y);
        a0.z = fmaf(v.z, w, a0.z); a0.w = fmaf(v.w, w, a0.w);
    }
    a0.x += (a1.x + a2.x) + a3.x;
    a0.y += (a1.y + a2.y) + a3.y;
    a0.z += (a1.z + a2.z) + a3.z;
    a0.w += (a1.w + a2.w) + a3.w;
    float inv = 1.0f / fmaxf((float)(end - off), 1.0f);
    a0.x *= inv; a0.y *= inv; a0.z *= inv; a0.w *= inv;
    reinterpret_cast<float4*>(g_agg1 + (size_t)n * D_IN)[lane] = a0;
}

// ---------------- layer 1 (tensor-core tf32 mma): h = relu([agg1|x] @ [Wl|Wr]^T + b) ----
#define LTC_WFLOATS (16 * 32 * 32 * 2)     // 32768 floats = 128 KB
#define LTC_FFLOATS (4 * 32 * 32 * 4)      // 16384 floats = 64 KB
#define LTC_SMEM_BYTES ((LTC_WFLOATS + LTC_FFLOATS) * 4)   // 196608
__global__ void layer1_tc_kernel(const float* __restrict__ x,
                                 const float* __restrict__ Wl,
                                 const float* __restrict__ bl,
                                 const float* __restrict__ Wr,
                                 float* __restrict__ hout) {
    extern __shared__ float sm[];
    float* Wf = sm;
    float* Ff = sm + LTC_WFLOATS;
    int t = threadIdx.x;

    for (int it = t; it < 128 * 64; it += 512) {
        int j = it >> 6, k4 = it & 63;
        int k0 = k4 * 4;
        float4 v = (k0 < 128)
            ? __ldg(reinterpret_cast<const float4*>(Wl + (size_t)j * 128 + k0))
            : __ldg(reinterpret_cast<const float4*>(Wr + (size_t)j * 128 + (k0 - 128)));
        int n_tile = j >> 3, g = j & 7;
        int ks = k0 >> 3, slot = (k0 & 7) >> 2;
        float* dst = Wf + ((n_tile * 32 + ks) * 32) * 2 + slot;
        int Lb = g * 4;
        dst[(Lb + 0) * 2] = tf32r(v.x);
        dst[(Lb + 1) * 2] = tf32r(v.y);
        dst[(Lb + 2) * 2] = tf32r(v.z);
        dst[(Lb + 3) * 2] = tf32r(v.w);
    }
    int warp = t >> 5, L = t & 31;
    int mw = warp >> 2, nw = warp & 3;
    int g = L >> 2, tg = L & 3;
    __syncthreads();

    const int NT = (N_NODES + 63) / 64;      // 1563
    for (int tile = blockIdx.x; tile < NT; tile += gridDim.x) {
        int base = tile * 64;
        __syncthreads();
        for (int it = t; it < 64 * 64; it += 512) {
            int nn = it >> 6, k4 = it & 63;
            int node = base + nn; if (node >= N_NODES) node = N_NODES - 1;
            int k0 = k4 * 4;
            float4 v = (k0 < 128)
                ? *reinterpret_cast<const float4*>(g_agg1 + (size_t)node * 128 + k0)
                : __ldg(reinterpret_cast<const float4*>(x + (size_t)node * 128 + (k0 - 128)));
            int m_tile = nn >> 4, r = nn & 15;
            int gg = r & 7, rowhi = r >> 3;
            int ks = k0 >> 3, colhi = (k0 & 7) >> 2;
            int f = rowhi + 2 * colhi;
            float* dst = Ff + ((m_tile * 32 + ks) * 32) * 4 + f;
            int Lb = gg * 4;
            dst[(Lb + 0) * 4] = tf32r(v.x);
            dst[(Lb + 1) * 4] = tf32r(v.y);
            dst[(Lb + 2) * 4] = tf32r(v.z);
            dst[(Lb + 3) * 4] = tf32r(v.w);
        }
        __syncthreads();
        float c[4][4];
        #pragma unroll
        for (int nt = 0; nt < 4; ++nt)
            c[nt][0] = c[nt][1] = c[nt][2] = c[nt][3] = 0.f;
        const float* fa = Ff + (mw * 32) * 128 + L * 4;
        #pragma unroll 4
        for (int ks = 0; ks < 32; ++ks) {
            float4 av = *reinterpret_cast<const float4*>(fa + ks * 128);
            unsigned a0 = __float_as_uint(av.x), a1 = __float_as_uint(av.y);
            unsigned a2 = __float_as_uint(av.z), a3 = __float_as_uint(av.w);
            #pragma unroll
            for (int nt = 0; nt < 4; ++nt) {
                const float* fb = Wf + ((nw * 4 + nt) * 32 + ks) * 64 + L * 2;
                float2 bv = *reinterpret_cast<const float2*>(fb);
                mma_tf32(c[nt][0], c[nt][1], c[nt][2], c[nt][3],
                         a0, a1, a2, a3,
                         __float_as_uint(bv.x), __float_as_uint(bv.y));
            }
        }
        int n0 = base + mw * 16 + g;
        int n1 = n0 + 8;
        #pragma unroll
        for (int nt = 0; nt < 4; ++nt) {
            int j0 = nw * 32 + nt * 8 + tg * 2;
            float b0 = __ldg(&bl[j0]), b1 = __ldg(&bl[j0 + 1]);
            if (n0 < N_NODES) {
                float2 o = make_float2(fmaxf(c[nt][0] + b0, 0.f),
                                       fmaxf(c[nt][1] + b1, 0.f));
                *reinterpret_cast<float2*>(&hout[(size_t)n0 * 128 + j0]) = o;
            }
            if (n1 < N_NODES) {
                float2 o = make_float2(fmaxf(c[nt][2] + b0, 0.f),
                                       fmaxf(c[nt][3] + b1, 0.f));
                *reinterpret_cast<float2*>(&hout[(size_t)n1 * 128 + j0]) = o;
            }
        }
    }
}

// ---------------- tmat2 (tensor-core tf32 mma, fused): [t|r] = h @ [Wl2|Wr2]^T -------
#define T2C_WFLOATS (16 * 16 * 32 * 2)     // 16384 floats = 64 KB
#define T2C_FFLOATS (4 * 16 * 32 * 4)      // 8192 floats = 32 KB
#define T2C_SMEM_BYTES ((T2C_WFLOATS + T2C_FFLOATS) * 4)   // 98304
__global__ void tmat2_tc_kernel(const float* __restrict__ h,
                                const float* __restrict__ Wl2,
                                const float* __restrict__ Wr2,
                                const float* __restrict__ b2) {
    extern __shared__ float sm[];
    float* Wf = sm;
    float* Ff = sm + T2C_WFLOATS;
    int t = threadIdx.x;

    for (int it = t; it < 128 * 32; it += 512) {
        int j = it >> 5, k4 = it & 31;
        int k0 = k4 * 4;
        float4 v = (j < 64)
            ? __ldg(reinterpret_cast<const float4*>(Wl2 + (size_t)j * 128 + k0))
            : __ldg(reinterpret_cast<const float4*>(Wr2 + (size_t)(j - 64) * 128 + k0));
        int n_tile = j >> 3, g = j & 7;
        int ks = k0 >> 3, slot = (k0 & 7) >> 2;
        float* dst = Wf + ((n_tile * 16 + ks) * 32) * 2 + slot;
        int Lb = g * 4;
        dst[(Lb + 0) * 2] = tf32r(v.x);
        dst[(Lb + 1) * 2] = tf32r(v.y);
        dst[(Lb + 2) * 2] = tf32r(v.z);
        dst[(Lb + 3) * 2] = tf32r(v.w);
    }
    int warp = t >> 5, L = t & 31;
    int mw = warp >> 2, nw = warp & 3;
    int g = L >> 2, tg = L & 3;
    __syncthreads();

    const int NT = (N_NODES + 63) / 64;      // 1563
    for (int tile = blockIdx.x; tile < NT; tile += gridDim.x) {
        int base = tile * 64;
        __syncthreads();
        for (int it = t; it < 64 * 32; it += 512) {
            int nn = it >> 5, k4 = it & 31;
            int node = base + nn; if (node >= N_NODES) node = N_NODES - 1;
            int k0 = k4 * 4;
            float4 v = *reinterpret_cast<const float4*>(h + (size_t)node * 128 + k0);
            int m_tile = nn >> 4, r = nn & 15;
            int gg = r & 7, rowhi = r >> 3;
            int ks = k0 >> 3, colhi = (k0 & 7) >> 2;
            int f = rowhi + 2 * colhi;
            float* dst = Ff + ((m_tile * 16 + ks) * 32) * 4 + f;
            int Lb = gg * 4;
            dst[(Lb + 0) * 4] = tf32r(v.x);
            dst[(Lb + 1) * 4] = tf32r(v.y);
            dst[(Lb + 2) * 4] = tf32r(v.z);
            dst[(Lb + 3) * 4] = tf32r(v.w);
        }
        __syncthreads();
        float c[4][4];
        #pragma unroll
        for (int nt = 0; nt < 4; ++nt)
            c[nt][0] = c[nt][1] = c[nt][2] = c[nt][3] = 0.f;
        const float* fa = Ff + (mw * 16) * 128 + L * 4;
        #pragma unroll 4
        for (int ks = 0; ks < 16; ++ks) {
            float4 av = *reinterpret_cast<const float4*>(fa + ks * 128);
            unsigned a0 = __float_as_uint(av.x), a1 = __float_as_uint(av.y);
            unsigned a2 = __float_as_uint(av.z), a3 = __float_as_uint(av.w);
            #pragma unroll
            for (int nt = 0; nt < 4; ++nt) {
                const float* fb = Wf + ((nw * 4 + nt) * 16 + ks) * 64 + L * 2;
                float2 bv = *reinterpret_cast<const float2*>(fb);
                mma_tf32(c[nt][0], c[nt][1], c[nt][2], c[nt][3],
                         a0, a1, a2, a3,
                         __float_as_uint(bv.x), __float_as_uint(bv.y));
            }
        }
        int n0 = base + mw * 16 + g;
        int n1 = n0 + 8;
        #pragma unroll
        for (int nt = 0; nt < 4; ++nt) {
            int j0 = nw * 32 + nt * 8 + tg * 2;
            if (j0 < 64) {
                if (n0 < N_NODES)
                    *reinterpret_cast<float2*>(&g_t[(size_t)n0 * 64 + j0]) =
                        make_float2(c[nt][0], c[nt][1]);
                if (n1 < N_NODES)
                    *reinterpret_cast<float2*>(&g_t[(size_t)n1 * 64 + j0]) =
                        make_float2(c[nt][2], c[nt][3]);
            } else {
                int jr = j0 - 64;
                float b0 = __ldg(&b2[jr]), b1 = __ldg(&b2[jr + 1]);
                if (n0 < N_NODES)
                    *reinterpret_cast<float2*>(&g_r[(size_t)n0 * 64 + jr]) =
                        make_float2(c[nt][0] + b0, c[nt][1] + b1);
                if (n1 < N_NODES)
                    *reinterpret_cast<float2*>(&g_r[(size_t)n1 * 64 + jr]) =
                        make_float2(c[nt][2] + b0, c[nt][3] + b1);
            }
        }
    }
}

// ---------------- gather2 + epilogue: out = mean-agg(t) + r ----------------
// HALF-warp per node (16 lanes x float4 = 64 ch); batches of 4 with edge prefetch
__global__ void gather2_kernel(float* __restrict__ out) {
    int gt = blockIdx.x * blockDim.x + threadIdx.x;
    int n = gt >> 4;
    if (n >= N_NODES) return;
    int sub = gt & 15;
    int off = g_off[n], end = g_off[n + 1];
    float4 rv = __ldg(reinterpret_cast<const float4*>(g_r + (size_t)n * D_OUT) + sub);
    float4 a0 = make_float4(0.f, 0.f, 0.f, 0.f);
    float4 a1 = a0, a2 = a0, a3 = a0;
    int i = off;
    int2 e0, e1, e2, e3;
    bool have = (i + 4 <= end);
    if (have) {
        e0 = __ldg(reinterpret_cast<const int2*>(g_edge) + i + 0);
        e1 = __ldg(reinterpret_cast<const int2*>(g_edge) + i + 1);
        e2 = __ldg(reinterpret_cast<const int2*>(g_edge) + i + 2);
        e3 = __ldg(reinterpret_cast<const int2*>(g_edge) + i + 3);
    }
    for (; i + 8 <= end; i += 4) {
        int2 f0 = __ldg(reinterpret_cast<const int2*>(g_edge) + i + 4);
        int2 f1 = __ldg(reinterpret_cast<const int2*>(g_edge) + i + 5);
        int2 f2 = __ldg(reinterpret_cast<const int2*>(g_edge) + i + 6);
        int2 f3 = __ldg(reinterpret_cast<const int2*>(g_edge) + i + 7);
        float4 v0 = __ldg(reinterpret_cast<const float4*>(g_t + (size_t)e0.x * D_OUT) + sub);
        float4 v1 = __ldg(reinterpret_cast<const float4*>(g_t + (size_t)e1.x * D_OUT) + sub);
        float4 v2 = __ldg(reinterpret_cast<const float4*>(g_t + (size_t)e2.x * D_OUT) + sub);
        float4 v3 = __ldg(reinterpret_cast<const float4*>(g_t + (size_t)e3.x * D_OUT) + sub);
        float w0 = __int_as_float(e0.y), w1 = __int_as_float(e1.y);
        float w2 = __int_as_float(e2.y), w3 = __int_as_float(e3.y);
        a0.x = fmaf(v0.x, w0, a0.x); a0.y = fmaf(v0.y, w0, a0.y);
        a0.z = fmaf(v0.z, w0, a0.z); a0.w = fmaf(v0.w, w0, a0.w);
        a1.x = fmaf(v1.x, w1, a1.x); a1.y = fmaf(v1.y, w1, a1.y);
        a1.z = fmaf(v1.z, w1, a1.z); a1.w = fmaf(v1.w, w1, a1.w);
        a2.x = fmaf(v2.x, w2, a2.x); a2.y = fmaf(v2.y, w2, a2.y);
        a2.z = fmaf(v2.z, w2, a2.z); a2.w = fmaf(v2.w, w2, a2.w);
        a3.x = fmaf(v3.x, w3, a3.x); a3.y = fmaf(v3.y, w3, a3.y);
        a3.z = fmaf(v3.z, w3, a3.z); a3.w = fmaf(v3.w, w3, a3.w);
        e0 = f0; e1 = f1; e2 = f2; e3 = f3;
    }
    if (have) {
        float4 v0 = __ldg(reinterpret_cast<const float4*>(g_t + (size_t)e0.x * D_OUT) + sub);
        float4 v1 = __ldg(reinterpret_cast<const float4*>(g_t + (size_t)e1.x * D_OUT) + sub);
        float4 v2 = __ldg(reinterpret_cast<const float4*>(g_t + (size_t)e2.x * D_OUT) + sub);
        float4 v3 = __ldg(reinterpret_cast<const float4*>(g_t + (size_t)e3.x * D_OUT) + sub);
        float w0 = __int_as_float(e0.y), w1 = __int_as_float(e1.y);
        float w2 = __int_as_float(e2.y), w3 = __int_as_float(e3.y);
        a0.x = fmaf(v0.x, w0, a0.x); a0.y = fmaf(v0.y, w0, a0.y);
        a0.z = fmaf(v0.z, w0, a0.z); a0.w = fmaf(v0.w, w0, a0.w);
        a1.x = fmaf(v1.x, w1, a1.x); a1.y = fmaf(v1.y, w1, a1.y);
        a1.z = fmaf(v1.z, w1, a1.z); a1.w = fmaf(v1.w, w1, a1.w);
        a2.x = fmaf(v2.x, w2, a2.x); a2.y = fmaf(v2.y, w2, a2.y);
        a2.z = fmaf(v2.z, w2, a2.z); a2.w = fmaf(v2.w, w2, a2.w);
        a3.x = fmaf(v3.x, w3, a3.x); a3.y = fmaf(v3.y, w3, a3.y);
        a3.z = fmaf(v3.z, w3, a3.z); a3.w = fmaf(v3.w, w3, a3.w);
        i += 4;
    }
    for (; i < end; ++i) {
        int2 e = __ldg(reinterpret_cast<const int2*>(g_edge) + i);
        float w = __int_as_float(e.y);
        float4 v = __ldg(reinterpret_cast<const float4*>(g_t + (size_t)e.x * D_OUT) + sub);
        a0.x = fmaf(v.x, w, a0.x); a0.y = fmaf(v.y, w, a0.y);
        a0.z = fmaf(v.z, w, a0.z); a0.w = fmaf(v.w, w, a0.w);
    }
    a0.x += (a1.x + a2.x) + a3.x;
    a0.y += (a1.y + a2.y) + a3.y;
    a0.z += (a1.z + a2.z) + a3.z;
    a0.w += (a1.w + a2.w) + a3.w;
    float inv = 1.0f / fmaxf((float)(end - off), 1.0f);
    a0.x = fmaf(a0.x, inv, rv.x);
    a0.y = fmaf(a0.y, inv, rv.y);
    a0.z = fmaf(a0.z, inv, rv.z);
    a0.w = fmaf(a0.w, inv, rv.w);
    reinterpret_cast<float4*>(out + (size_t)n * D_OUT)[sub] = a0;
}

// ---------------- launch ----------------
extern "C" void kernel_launch(void* const* d_in, const int* in_sizes, int n_in,
                              void* d_out, int out_size) {
    (void)in_sizes; (void)n_in;
    const float* x   = (const float*)d_in[0];
    const void*  ei  = d_in[1];                 // int32 or int64, detected on device
    const float* ew  = (const float*)d_in[2];
    const float* Wl1 = (const float*)d_in[3];
    const float* bl1 = (const float*)d_in[4];
    const float* Wr1 = (const float*)d_in[5];
    const float* Wl2 = (const float*)d_in[6];
    const float* bl2 = (const float*)d_in[7];
    const float* Wr2 = (const float*)d_in[8];

    float* hptr;
    float* lptr;
    const size_t full = (size_t)N_NODES * (D_HID + D_OUT);
    if ((size_t)out_size >= full) {
        hptr = (float*)d_out;
        lptr = hptr + (size_t)N_NODES * D_HID;
    } else {
        void* sym = nullptr;
        cudaGetSymbolAddress(&sym, g_h);
        hptr = (float*)sym;
        lptr = (float*)d_out;
    }

    int smcount = 148;
    if (cudaDeviceGetAttribute(&smcount, cudaDevAttrMultiProcessorCount, 0) != cudaSuccess)
        smcount = 148;

    cudaFuncSetAttribute(layer1_tc_kernel,
                         cudaFuncAttributeMaxDynamicSharedMemorySize, LTC_SMEM_BYTES);
    cudaFuncSetAttribute(tmat2_tc_kernel,
                         cudaFuncAttributeMaxDynamicSharedMemorySize, T2C_SMEM_BYTES);

    detect_zero_kernel<<<NBLK, 256>>>((const int*)ei);       // 1
    hist_kernel<<<N_EDGES / 4 / 256, 256>>>(ei);             // 2
    blocksum_kernel<<<NBLK, 256>>>();                        // 3
    offsets_kernel<<<NBLK, 512>>>();                         // 4
    fill_kernel<<<N_EDGES / 4 / 256, 256>>>(ei, ew);         // 5
    gather1_kernel<<<(N_NODES * 32 + 255) / 256, 256>>>(x);  // 6
    layer1_tc_kernel<<<smcount, 512, LTC_SMEM_BYTES>>>(x, Wl1, bl1, Wr1, hptr);
    tmat2_tc_kernel<<<2 * smcount, 512, T2C_SMEM_BYTES>>>(hptr, Wl2, Wr2, bl2);
    gather2_kernel<<<(N_NODES * 16 + 255) / 256, 256>>>(lptr);
}